// round 3
// baseline (speedup 1.0000x reference)
#include <cuda_runtime.h>
#include <cstdint>

// ---------------------------------------------------------------------------
#define BATCH   16384
#define D_IN    256
#define D_H     512
#define NQ      12
#define NLAYERS 4
#define FULLM   0xffffffffu

typedef unsigned long long ull;

// Scratch for h = relu(data @ W_graph + b_graph): 16384 x 512 fp32 = 32 MB
__device__ float g_h[(size_t)BATCH * D_H];

__host__ __device__ constexpr int cpop(int v) {
    int c = 0;
    for (int i = 0; i < 12; i++) c += (v >> i) & 1;
    return c;
}

// ---- packed f32x2 helpers (sm_100a) ----
__device__ __forceinline__ ull pk2(float x, float y) {
    ull r; asm("mov.b64 %0, {%1,%2};" : "=l"(r) : "f"(x), "f"(y)); return r;
}
__device__ __forceinline__ ull pkb(float x) { return pk2(x, x); }
__device__ __forceinline__ void upk(ull v, float& x, float& y) {
    asm("mov.b64 {%0,%1}, %2;" : "=f"(x), "=f"(y) : "l"(v));
}
__device__ __forceinline__ ull fma2(ull a, ull b, ull c) {
    ull d; asm("fma.rn.f32x2 %0, %1, %2, %3;" : "=l"(d) : "l"(a), "l"(b), "l"(c)); return d;
}
__device__ __forceinline__ ull mul2(ull a, ull b) {
    ull d; asm("mul.rn.f32x2 %0, %1, %2;" : "=l"(d) : "l"(a), "l"(b)); return d;
}
__device__ __forceinline__ ull add2(ull a, ull b) {
    ull d; asm("add.rn.f32x2 %0, %1, %2;" : "=l"(d) : "l"(a), "l"(b)); return d;
}

// ---------------------------------------------------------------------------
// Kernel 1: h = relu(data @ W_graph + b_graph)  (unchanged: ~SIMT fp32 roofline)
// ---------------------------------------------------------------------------
__global__ void __launch_bounds__(256)
gemm_relu_kernel(const float* __restrict__ A,
                 const float* __restrict__ B,
                 const float* __restrict__ bias)
{
    __shared__ float As[8][128];
    __shared__ float Bs[8][128];

    const int tid = threadIdx.x;
    const int colBase = blockIdx.x * 128;
    const int rowBase = blockIdx.y * 128;

    const int innerRowA = tid >> 1;
    const int innerColA = (tid & 1) * 4;
    const int innerRowB = tid >> 5;
    const int innerColB = (tid & 31) * 4;

    const int tr = (tid >> 4) * 8;
    const int tc = (tid & 15) * 8;

    float acc[8][8];
#pragma unroll
    for (int i = 0; i < 8; i++)
#pragma unroll
        for (int j = 0; j < 8; j++) acc[i][j] = 0.f;

    const float* Aptr = A + (size_t)(rowBase + innerRowA) * D_IN + innerColA;
    const float* Bptr = B + (size_t)innerRowB * D_H + colBase + innerColB;

    for (int k0 = 0; k0 < D_IN; k0 += 8) {
        float4 av = *reinterpret_cast<const float4*>(Aptr + k0);
        float4 bv = *reinterpret_cast<const float4*>(Bptr + (size_t)k0 * D_H);

        As[innerColA + 0][innerRowA] = av.x;
        As[innerColA + 1][innerRowA] = av.y;
        As[innerColA + 2][innerRowA] = av.z;
        As[innerColA + 3][innerRowA] = av.w;
        *reinterpret_cast<float4*>(&Bs[innerRowB][innerColB]) = bv;
        __syncthreads();

#pragma unroll
        for (int kk = 0; kk < 8; kk++) {
            float ra[8], rb[8];
            float4 a0 = *reinterpret_cast<const float4*>(&As[kk][tr]);
            float4 a1 = *reinterpret_cast<const float4*>(&As[kk][tr + 4]);
            float4 b0 = *reinterpret_cast<const float4*>(&Bs[kk][tc]);
            float4 b1 = *reinterpret_cast<const float4*>(&Bs[kk][tc + 4]);
            ra[0] = a0.x; ra[1] = a0.y; ra[2] = a0.z; ra[3] = a0.w;
            ra[4] = a1.x; ra[5] = a1.y; ra[6] = a1.z; ra[7] = a1.w;
            rb[0] = b0.x; rb[1] = b0.y; rb[2] = b0.z; rb[3] = b0.w;
            rb[4] = b1.x; rb[5] = b1.y; rb[6] = b1.z; rb[7] = b1.w;
#pragma unroll
            for (int i = 0; i < 8; i++)
#pragma unroll
                for (int j = 0; j < 8; j++)
                    acc[i][j] = fmaf(ra[i], rb[j], acc[i][j]);
        }
        __syncthreads();
    }

#pragma unroll
    for (int i = 0; i < 8; i++) {
        const int row = rowBase + tr + i;
#pragma unroll
        for (int j = 0; j < 8; j += 4) {
            const int col = colBase + tc + j;
            float4 v;
            v.x = fmaxf(acc[i][j + 0] + bias[col + 0], 0.f);
            v.y = fmaxf(acc[i][j + 1] + bias[col + 1], 0.f);
            v.z = fmaxf(acc[i][j + 2] + bias[col + 2], 0.f);
            v.w = fmaxf(acc[i][j + 3] + bias[col + 3], 0.f);
            *reinterpret_cast<float4*>(&g_h[(size_t)row * D_H + col]) = v;
        }
    }
}

// ---------------------------------------------------------------------------
// Kernel 2: fused GEMM2 -> 12-qubit sim -> expectation, 2 samples packed f32x2.
//
// Block = 128 threads = one sample PAIR (s0 = 2*blk, s1 = 2*blk+1), each thread
// holds 32 f32x2 amplitudes (.x = s0, .y = s1).
//
// Layout A: logical m = (r<<7) | (w<<5) | lane
//   reg bit t  = m bit 7+t  (wires 0..4, wire u <-> bt = 4-u)
//   warp bits  = m bits 6,5 (wires 5,6)
//   lane bit b = m bit b    (wires 7..11)
// Layout B: m = (w<<10) | (lane<<5) | r
//   reg bit t  = m bit t    (wires 7..11, bt = 11-u)
//   lane bit 0 = m bit 5 (wire 6), lane bit 1 = m bit 6 (wire 5) -> shfl_xor
// Per layer: wires0-4 (reg FMA2, A) -> smem A->B -> wires7-11 (reg FMA2, B)
//   -> wires5,6 (64-bit shfl_xor + FMA2) -> smem trip applying the CNOT-chain
//   Gray permutation st'[m] = v[m ^ (m>>1)] and returning to layout A.
// RY in tan-form (coefficients batch-shared -> broadcast {t,t}); all 48 cos
// factors folded into the initial amplitudes. Swizzle phys = e ^ ((e>>5)&31)
// is bank-conflict-free in all four smem phases.
// ---------------------------------------------------------------------------
__global__ void __launch_bounds__(128, 3)
sim_kernel(const float* __restrict__ Wp,   // [D_H, NQ]
           const float* __restrict__ bp,   // [NQ]
           const float* __restrict__ qw,   // [NLAYERS*NQ]
           float* __restrict__ out)        // [BATCH]
{
    __shared__ ull stb[4096];              // 32 KB: 4096 packed amplitudes
    __shared__ float qt[NLAYERS * NQ];
    __shared__ float cS[2][NQ], sS[2][NQ];
    __shared__ float xpart[2][2][NQ];
    __shared__ float2 redc[4];
    __shared__ float CfS;

    const int tid = threadIdx.x;
    if (tid < NLAYERS * NQ) {
        float a = qw[tid] * 0.5f;
        float sv, cv;
        sincosf(a, &sv, &cv);
        qt[tid] = sv / cv;
    }
    if (tid == 0) {
        float C = 1.f;
        for (int i = 0; i < NLAYERS * NQ; i++) C *= cosf(qw[i] * 0.5f);
        CfS = C;
    }

    const int w    = tid >> 5;      // 0..3
    const int lane = tid & 31;
    const int s0   = blockIdx.x * 2;

    // ---- GEMM2: warps {0,1} -> sample 0, {2,3} -> sample 1 (split K=512) ----
    {
        const float* hr = g_h + (size_t)(s0 + (w >> 1)) * D_H;
        float xa[NQ];
#pragma unroll
        for (int q = 0; q < NQ; q++) xa[q] = 0.f;
#pragma unroll
        for (int j = 0; j < 8; j++) {
            const int k = (w & 1) * 256 + j * 32 + lane;
            const float hv = hr[k];
            const float4* wr = reinterpret_cast<const float4*>(Wp + (size_t)k * NQ);
            float4 w0 = wr[0], w1 = wr[1], w2 = wr[2];
            xa[0]  = fmaf(hv, w0.x, xa[0]);
            xa[1]  = fmaf(hv, w0.y, xa[1]);
            xa[2]  = fmaf(hv, w0.z, xa[2]);
            xa[3]  = fmaf(hv, w0.w, xa[3]);
            xa[4]  = fmaf(hv, w1.x, xa[4]);
            xa[5]  = fmaf(hv, w1.y, xa[5]);
            xa[6]  = fmaf(hv, w1.z, xa[6]);
            xa[7]  = fmaf(hv, w1.w, xa[7]);
            xa[8]  = fmaf(hv, w2.x, xa[8]);
            xa[9]  = fmaf(hv, w2.y, xa[9]);
            xa[10] = fmaf(hv, w2.z, xa[10]);
            xa[11] = fmaf(hv, w2.w, xa[11]);
        }
#pragma unroll
        for (int q = 0; q < NQ; q++) {
            float v = xa[q];
#pragma unroll
            for (int o = 16; o; o >>= 1) v += __shfl_xor_sync(FULLM, v, o);
            if (lane == q) xpart[w >> 1][w & 1][q] = v;
        }
    }
    __syncthreads();
    if ((w & 1) == 0 && lane < NQ) {
        const int smp = w >> 1;
        float x = xpart[smp][0][lane] + xpart[smp][1][lane] + bp[lane];
        float half = fmaf(0.5f, atanf(x), 0.78539816339744831f);
        float sv, cv;
        sincosf(half, &sv, &cv);
        cS[smp][lane] = cv;
        sS[smp][lane] = sv;
    }
    __syncthreads();

    // ---- initial product state, layout A ----
    float bx = CfS, by = CfS;
#pragma unroll
    for (int b = 0; b < 5; b++) {
        const int wr = 11 - b;
        if ((lane >> b) & 1) { bx *= sS[0][wr]; by *= sS[1][wr]; }
        else                 { bx *= cS[0][wr]; by *= cS[1][wr]; }
    }
    if (w & 1)  { bx *= sS[0][6]; by *= sS[1][6]; }
    else        { bx *= cS[0][6]; by *= cS[1][6]; }
    if (w >> 1) { bx *= sS[0][5]; by *= sS[1][5]; }
    else        { bx *= cS[0][5]; by *= cS[1][5]; }

    ull st[32];
    st[0] = pk2(bx, by);
#pragma unroll
    for (int tb = 0; tb < 5; tb++) {
        const int wirew = 4 - tb;
        const ull cp = pk2(cS[0][wirew], cS[1][wirew]);
        const ull sp = pk2(sS[0][wirew], sS[1][wirew]);
#pragma unroll
        for (int r = 0; r < (1 << tb); r++) {
            st[r | (1 << tb)] = mul2(st[r], sp);
            st[r] = mul2(st[r], cp);
        }
    }

    const int ebase = (w << 10) | (lane << 5);

    // ---- layers ----
#pragma unroll 1
    for (int ell = 0; ell < NLAYERS; ell++) {
        const int qb = ell * NQ;

        // wires 0..4 on layout-A reg bits (bt = 4-u)
#pragma unroll
        for (int u = 0; u < 5; u++) {
            const float t = qt[qb + u];
            const ull tp = pkb(t), np = pkb(-t);
            const int bt = 4 - u;
#pragma unroll
            for (int r = 0; r < 32; r++) {
                if (((r >> bt) & 1) == 0) {
                    const int j = r | (1 << bt);
                    const ull A = st[r], B = st[j];
                    st[r] = fma2(np, B, A);
                    st[j] = fma2(tp, A, B);
                }
            }
        }

        // trip 1: A -> B
        __syncthreads();
#pragma unroll
        for (int r = 0; r < 32; r++) {
            const int e = (r << 7) | tid;
            stb[e ^ ((e >> 5) & 31)] = st[r];
        }
        __syncthreads();
#pragma unroll
        for (int r = 0; r < 32; r++)
            st[r] = stb[ebase | (r ^ lane)];

        // wires 7..11 on layout-B reg bits (bt = 11-u)
#pragma unroll
        for (int u = 7; u < 12; u++) {
            const float t = qt[qb + u];
            const ull tp = pkb(t), np = pkb(-t);
            const int bt = 11 - u;
#pragma unroll
            for (int r = 0; r < 32; r++) {
                if (((r >> bt) & 1) == 0) {
                    const int j = r | (1 << bt);
                    const ull A = st[r], B = st[j];
                    st[r] = fma2(np, B, A);
                    st[j] = fma2(tp, A, B);
                }
            }
        }

        // wire 6 (m bit5 = lane bit0) and wire 5 (m bit6 = lane bit1): shfl
        {
            const float t6 = qt[qb + 6];
            const ull sg6 = (lane & 1) ? pkb(t6) : pkb(-t6);
#pragma unroll
            for (int r = 0; r < 32; r++) {
                const ull p = __shfl_xor_sync(FULLM, st[r], 1);
                st[r] = fma2(sg6, p, st[r]);
            }
            const float t5 = qt[qb + 5];
            const ull sg5 = ((lane >> 1) & 1) ? pkb(t5) : pkb(-t5);
#pragma unroll
            for (int r = 0; r < 32; r++) {
                const ull p = __shfl_xor_sync(FULLM, st[r], 2);
                st[r] = fma2(sg5, p, st[r]);
            }
        }

        // trip 2: write B, read Gray-permuted -> layout A
        __syncthreads();
#pragma unroll
        for (int r = 0; r < 32; r++)
            stb[ebase | (r ^ lane)] = st[r];
        __syncthreads();
#pragma unroll
        for (int r = 0; r < 32; r++) {
            const int n = (r << 7) | tid;
            const int p = n ^ (n >> 1);
            st[r] = stb[p ^ ((p >> 5) & 31)];
        }
    }

    // ---- measurement: sum st^2 * (12 - 2*popc(m)), m = (r<<7)|tid ----
    ull KK[6];
#pragma unroll
    for (int i = 0; i < 6; i++) KK[i] = pkb((float)(NQ - 2 * i));
    ull acc1 = 0ull, acc2 = 0ull;
#pragma unroll
    for (int r = 0; r < 32; r++) {
        const ull t = mul2(st[r], st[r]);
        acc1 = fma2(KK[cpop(r)], t, acc1);
        acc2 = add2(acc2, t);
    }
    const float pw = -2.0f * (float)__popc(tid);
    const ull res = fma2(pkb(pw), acc2, acc1);
    float rx, ry;
    upk(res, rx, ry);
#pragma unroll
    for (int o = 16; o; o >>= 1) {
        rx += __shfl_xor_sync(FULLM, rx, o);
        ry += __shfl_xor_sync(FULLM, ry, o);
    }
    if (lane == 0) redc[w] = make_float2(rx, ry);
    __syncthreads();
    if (tid == 0) {
        out[s0]     = redc[0].x + redc[1].x + redc[2].x + redc[3].x;
        out[s0 + 1] = redc[0].y + redc[1].y + redc[2].y + redc[3].y;
    }
}

// ---------------------------------------------------------------------------
extern "C" void kernel_launch(void* const* d_in, const int* in_sizes, int n_in,
                              void* d_out, int out_size)
{
    const float* data = (const float*)d_in[0];
    const float* Wg   = (const float*)d_in[1];
    const float* bg   = (const float*)d_in[2];
    const float* Wp   = (const float*)d_in[3];
    const float* bp   = (const float*)d_in[4];
    const float* qw   = (const float*)d_in[5];
    float* out = (float*)d_out;

    dim3 gGrid(D_H / 128, BATCH / 128);
    gemm_relu_kernel<<<gGrid, 256>>>(data, Wg, bg);

    sim_kernel<<<BATCH / 2, 128>>>(Wp, bp, qw, out);
}

// round 4
// speedup vs baseline: 1.2670x; 1.2670x over previous
#include <cuda_runtime.h>
#include <cstdint>

// ---------------------------------------------------------------------------
#define BATCH   16384
#define D_IN    256
#define D_H     512
#define NQ      12
#define NLAYERS 4
#define FULLM   0xffffffffu

typedef unsigned long long ull;

// Scratch for h = relu(data @ W_graph + b_graph): 16384 x 512 fp32 = 32 MB
__device__ float g_h[(size_t)BATCH * D_H];

__host__ __device__ constexpr int cpop(int v) {
    int c = 0;
    for (int i = 0; i < 12; i++) c += (v >> i) & 1;
    return c;
}
__host__ __device__ constexpr int e5(int r) {            // 5-bit prefix-xor
    return (r ^ (r >> 1) ^ (r >> 2) ^ (r >> 3) ^ (r >> 4)) & 31;
}
__host__ __device__ constexpr int gray5(int r) { return (r ^ (r >> 1)) & 31; }

// ---- packed f32x2 helpers (sm_100a) ----
__device__ __forceinline__ ull pk2(float x, float y) {
    ull r; asm("mov.b64 %0, {%1,%2};" : "=l"(r) : "f"(x), "f"(y)); return r;
}
__device__ __forceinline__ ull pkb(float x) { return pk2(x, x); }
__device__ __forceinline__ void upk(ull v, float& x, float& y) {
    asm("mov.b64 {%0,%1}, %2;" : "=f"(x), "=f"(y) : "l"(v));
}
__device__ __forceinline__ ull fma2(ull a, ull b, ull c) {
    ull d; asm("fma.rn.f32x2 %0, %1, %2, %3;" : "=l"(d) : "l"(a), "l"(b), "l"(c)); return d;
}
__device__ __forceinline__ ull mul2(ull a, ull b) {
    ull d; asm("mul.rn.f32x2 %0, %1, %2;" : "=l"(d) : "l"(a), "l"(b)); return d;
}
__device__ __forceinline__ ull add2(ull a, ull b) {
    ull d; asm("add.rn.f32x2 %0, %1, %2;" : "=l"(d) : "l"(a), "l"(b)); return d;
}

// ---------------------------------------------------------------------------
// Kernel 1: h = relu(data @ W_graph + b_graph)  (unchanged)
// ---------------------------------------------------------------------------
__global__ void __launch_bounds__(256)
gemm_relu_kernel(const float* __restrict__ A,
                 const float* __restrict__ B,
                 const float* __restrict__ bias)
{
    __shared__ float As[8][128];
    __shared__ float Bs[8][128];

    const int tid = threadIdx.x;
    const int colBase = blockIdx.x * 128;
    const int rowBase = blockIdx.y * 128;

    const int innerRowA = tid >> 1;
    const int innerColA = (tid & 1) * 4;
    const int innerRowB = tid >> 5;
    const int innerColB = (tid & 31) * 4;

    const int tr = (tid >> 4) * 8;
    const int tc = (tid & 15) * 8;

    float acc[8][8];
#pragma unroll
    for (int i = 0; i < 8; i++)
#pragma unroll
        for (int j = 0; j < 8; j++) acc[i][j] = 0.f;

    const float* Aptr = A + (size_t)(rowBase + innerRowA) * D_IN + innerColA;
    const float* Bptr = B + (size_t)innerRowB * D_H + colBase + innerColB;

    for (int k0 = 0; k0 < D_IN; k0 += 8) {
        float4 av = *reinterpret_cast<const float4*>(Aptr + k0);
        float4 bv = *reinterpret_cast<const float4*>(Bptr + (size_t)k0 * D_H);

        As[innerColA + 0][innerRowA] = av.x;
        As[innerColA + 1][innerRowA] = av.y;
        As[innerColA + 2][innerRowA] = av.z;
        As[innerColA + 3][innerRowA] = av.w;
        *reinterpret_cast<float4*>(&Bs[innerRowB][innerColB]) = bv;
        __syncthreads();

#pragma unroll
        for (int kk = 0; kk < 8; kk++) {
            float ra[8], rb[8];
            float4 a0 = *reinterpret_cast<const float4*>(&As[kk][tr]);
            float4 a1 = *reinterpret_cast<const float4*>(&As[kk][tr + 4]);
            float4 b0 = *reinterpret_cast<const float4*>(&Bs[kk][tc]);
            float4 b1 = *reinterpret_cast<const float4*>(&Bs[kk][tc + 4]);
            ra[0] = a0.x; ra[1] = a0.y; ra[2] = a0.z; ra[3] = a0.w;
            ra[4] = a1.x; ra[5] = a1.y; ra[6] = a1.z; ra[7] = a1.w;
            rb[0] = b0.x; rb[1] = b0.y; rb[2] = b0.z; rb[3] = b0.w;
            rb[4] = b1.x; rb[5] = b1.y; rb[6] = b1.z; rb[7] = b1.w;
#pragma unroll
            for (int i = 0; i < 8; i++)
#pragma unroll
                for (int j = 0; j < 8; j++)
                    acc[i][j] = fmaf(ra[i], rb[j], acc[i][j]);
        }
        __syncthreads();
    }

#pragma unroll
    for (int i = 0; i < 8; i++) {
        const int row = rowBase + tr + i;
#pragma unroll
        for (int j = 0; j < 8; j += 4) {
            const int col = colBase + tc + j;
            float4 v;
            v.x = fmaxf(acc[i][j + 0] + bias[col + 0], 0.f);
            v.y = fmaxf(acc[i][j + 1] + bias[col + 1], 0.f);
            v.z = fmaxf(acc[i][j + 2] + bias[col + 2], 0.f);
            v.w = fmaxf(acc[i][j + 3] + bias[col + 3], 0.f);
            *reinterpret_cast<float4*>(&g_h[(size_t)row * D_H + col]) = v;
        }
    }
}

// ---------------------------------------------------------------------------
// Kernel 2: fused GEMM2 -> sim -> expectation. 2 samples per block (f32x2).
//
// Identities used:
//  * Layer-1 RYs merge into the data-dependent initial RYs (additive angles).
//  * Each CNOT chain is the Gray perm P(m)=m^(m>>1); every P composes for
//    free into the next A->B smem transpose; the final P folds into the
//    measurement weights via popc(E(q)) = popc(E5(r)) + (par(r)?7-Pt:Pt).
//  * RY in tan form; cos factors of layers 2..4 folded into the init state.
//
// Layout A: q = (r<<7)|tid  (reg bits = wires 0..4, warp bits = wires 5,6,
//           lane bits = wires 7..11)
// Layout B: q = (w<<10)|(lane<<5)|r  (reg bits = wires 7..11; lane bits 0,1
//           = wires 6,5 -> shfl_xor 1/2)
// Per remaining layer (3 of them):
//   trip A->B (composed with P) -> wires 7..11 (reg) + 6,5 (shfl)
//   -> trip B->A -> wires 0..4 (reg)
// Trips are double-buffered (one barrier each): 6 barriers total.
// ---------------------------------------------------------------------------
__global__ void __launch_bounds__(128, 3)
sim_kernel(const float* __restrict__ Wp,   // [D_H, NQ]
           const float* __restrict__ bp,   // [NQ]
           const float* __restrict__ qw,   // [NLAYERS*NQ]
           float* __restrict__ out)        // [BATCH]
{
    extern __shared__ ull dynbuf[];        // 2 x 4096 packed amplitudes (64 KB)
    __shared__ float qt[NLAYERS * NQ];
    __shared__ float cS[2][NQ], sS[2][NQ];
    __shared__ float xpart[2][2][NQ];
    __shared__ float2 redc[4];
    __shared__ float CfS;

    const int tid  = threadIdx.x;
    const int w    = tid >> 5;      // 0..3
    const int lane = tid & 31;
    const int s0   = blockIdx.x * 2;

    if (tid < NLAYERS * NQ) {
        float a = qw[tid] * 0.5f;
        float sv, cv;
        sincosf(a, &sv, &cv);
        qt[tid] = sv / cv;
    }
    if (tid == 0) {
        float C = 1.f;
        for (int i = NQ; i < NLAYERS * NQ; i++) C *= cosf(qw[i] * 0.5f);
        CfS = C;
    }

    // ---- GEMM2: warps {0,1} -> sample 0, {2,3} -> sample 1 (split K=512) ----
    {
        const float* hr = g_h + (size_t)(s0 + (w >> 1)) * D_H;
        float xa[NQ];
#pragma unroll
        for (int q = 0; q < NQ; q++) xa[q] = 0.f;
#pragma unroll
        for (int j = 0; j < 8; j++) {
            const int k = (w & 1) * 256 + j * 32 + lane;
            const float hv = hr[k];
            const float4* wr = reinterpret_cast<const float4*>(Wp + (size_t)k * NQ);
            float4 w0 = wr[0], w1 = wr[1], w2 = wr[2];
            xa[0]  = fmaf(hv, w0.x, xa[0]);
            xa[1]  = fmaf(hv, w0.y, xa[1]);
            xa[2]  = fmaf(hv, w0.z, xa[2]);
            xa[3]  = fmaf(hv, w0.w, xa[3]);
            xa[4]  = fmaf(hv, w1.x, xa[4]);
            xa[5]  = fmaf(hv, w1.y, xa[5]);
            xa[6]  = fmaf(hv, w1.z, xa[6]);
            xa[7]  = fmaf(hv, w1.w, xa[7]);
            xa[8]  = fmaf(hv, w2.x, xa[8]);
            xa[9]  = fmaf(hv, w2.y, xa[9]);
            xa[10] = fmaf(hv, w2.z, xa[10]);
            xa[11] = fmaf(hv, w2.w, xa[11]);
        }
#pragma unroll
        for (int q = 0; q < NQ; q++) {
            float v = xa[q];
#pragma unroll
            for (int o = 16; o; o >>= 1) v += __shfl_xor_sync(FULLM, v, o);
            if (lane == q) xpart[w >> 1][w & 1][q] = v;
        }
    }
    __syncthreads();
    if ((w & 1) == 0 && lane < NQ) {
        const int smp = w >> 1;
        float x = xpart[smp][0][lane] + xpart[smp][1][lane] + bp[lane];
        // merged: 0.5*(atan(x)+pi/2) + 0.5*qw[layer0, wire=lane]
        float half = fmaf(0.5f, atanf(x), 0.78539816339744831f)
                   + 0.5f * qw[lane];
        float sv, cv;
        sincosf(half, &sv, &cv);
        cS[smp][lane] = cv;
        sS[smp][lane] = sv;
    }
    __syncthreads();

    // ---- initial product state, layout A (includes merged layer-1 RYs) ----
    float bx = CfS, by = CfS;
#pragma unroll
    for (int b = 0; b < 5; b++) {
        const int wr = 11 - b;
        if ((lane >> b) & 1) { bx *= sS[0][wr]; by *= sS[1][wr]; }
        else                 { bx *= cS[0][wr]; by *= cS[1][wr]; }
    }
    if (w & 1)  { bx *= sS[0][6]; by *= sS[1][6]; }
    else        { bx *= cS[0][6]; by *= cS[1][6]; }
    if (w >> 1) { bx *= sS[0][5]; by *= sS[1][5]; }
    else        { bx *= cS[0][5]; by *= cS[1][5]; }

    ull st[32];
    st[0] = pk2(bx, by);
#pragma unroll
    for (int tb = 0; tb < 5; tb++) {
        const int wirew = 4 - tb;
        const ull cp = pk2(cS[0][wirew], cS[1][wirew]);
        const ull sp = pk2(sS[0][wirew], sS[1][wirew]);
#pragma unroll
        for (int r = 0; r < (1 << tb); r++) {
            st[r | (1 << tb)] = mul2(st[r], sp);
            st[r] = mul2(st[r], cp);
        }
    }

    // ---- precomputed smem address bases ----
    const int tA  = tid ^ ((tid >> 5) & 3);          // write/read layout-A base
    const int WB2 = (w << 10) | (lane << 5);         // write layout-B base
    int RB1;                                         // A->B-with-gray read base
    {
        const int n0 = WB2;
        const int g0 = n0 ^ (n0 >> 1);
        RB1 = g0 ^ ((g0 >> 5) & 31);
    }
    ull* S0 = dynbuf;
    ull* S1 = dynbuf + 4096;

    // ---- 3 remaining layers ----
#pragma unroll 1
    for (int ell = 0; ell < 3; ell++) {
        const int qb = NQ * (ell + 1);

        // trip: A -> B composed with gray perm (buffer S0)
#pragma unroll
        for (int r = 0; r < 32; r++)
            S0[(r << 7) + (tA ^ ((r & 7) << 2))] = st[r];
        __syncthreads();
#pragma unroll
        for (int r = 0; r < 32; r++)
            st[r] = S0[RB1 ^ gray5(r)];

        // wires 7..11 on layout-B reg bits (bt = 11-u)
#pragma unroll
        for (int u = 7; u < 12; u++) {
            const float t = qt[qb + u];
            const ull tp = pkb(t), np = pkb(-t);
            const int bt = 11 - u;
#pragma unroll
            for (int r = 0; r < 32; r++) {
                if (((r >> bt) & 1) == 0) {
                    const int j = r | (1 << bt);
                    const ull A = st[r], B = st[j];
                    st[r] = fma2(np, B, A);
                    st[j] = fma2(tp, A, B);
                }
            }
        }

        // wire 6 (lane bit 0) and wire 5 (lane bit 1): 64-bit shfl_xor
        {
            const float t6 = qt[qb + 6];
            const ull sg6 = (lane & 1) ? pkb(t6) : pkb(-t6);
#pragma unroll
            for (int r = 0; r < 32; r++) {
                const ull p = __shfl_xor_sync(FULLM, st[r], 1);
                st[r] = fma2(sg6, p, st[r]);
            }
            const float t5 = qt[qb + 5];
            const ull sg5 = ((lane >> 1) & 1) ? pkb(t5) : pkb(-t5);
#pragma unroll
            for (int r = 0; r < 32; r++) {
                const ull p = __shfl_xor_sync(FULLM, st[r], 2);
                st[r] = fma2(sg5, p, st[r]);
            }
        }

        // trip: B -> A (buffer S1)
#pragma unroll
        for (int r = 0; r < 32; r++)
            S1[WB2 | (lane ^ r)] = st[r];
        __syncthreads();
#pragma unroll
        for (int r = 0; r < 32; r++)
            st[r] = S1[(r << 7) + (tA ^ ((r & 7) << 2))];

        // wires 0..4 on layout-A reg bits (bt = 4-u)
#pragma unroll
        for (int u = 0; u < 5; u++) {
            const float t = qt[qb + u];
            const ull tp = pkb(t), np = pkb(-t);
            const int bt = 4 - u;
#pragma unroll
            for (int r = 0; r < 32; r++) {
                if (((r >> bt) & 1) == 0) {
                    const int j = r | (1 << bt);
                    const ull A = st[r], B = st[j];
                    st[r] = fma2(np, B, A);
                    st[j] = fma2(tp, A, B);
                }
            }
        }
    }

    // ---- measurement with final gray perm folded into the weights ----
    // weight(q) = 12 - 2*popc(E12(q)), q = (r<<7)|tid
    //           = A_r + s_r * 2*Pt,  Pt = popc(E7(tid))
    int ex = tid;
    ex ^= ex >> 1; ex ^= ex >> 2; ex ^= ex >> 4;
    const int Pt = __popc(ex & 127);

    ull acc1 = 0ull, accP = 0ull, accM = 0ull;
#pragma unroll
    for (int r = 0; r < 32; r++) {
        const int a = cpop(e5(r));
        const int p = cpop(r) & 1;
        const float Ar = p ? (float)(-2 - 2 * a) : (float)(12 - 2 * a);
        const ull t = mul2(st[r], st[r]);
        acc1 = fma2(pkb(Ar), t, acc1);
        if (p) accP = add2(accP, t);
        else   accM = add2(accM, t);
    }
    const ull S = fma2(pkb(-1.f), accM, accP);     // sum s_r * t_r
    const ull res = fma2(pkb(2.f * (float)Pt), S, acc1);

    float rx, ry;
    upk(res, rx, ry);
#pragma unroll
    for (int o = 16; o; o >>= 1) {
        rx += __shfl_xor_sync(FULLM, rx, o);
        ry += __shfl_xor_sync(FULLM, ry, o);
    }
    if (lane == 0) redc[w] = make_float2(rx, ry);
    __syncthreads();
    if (tid == 0) {
        out[s0]     = redc[0].x + redc[1].x + redc[2].x + redc[3].x;
        out[s0 + 1] = redc[0].y + redc[1].y + redc[2].y + redc[3].y;
    }
}

// ---------------------------------------------------------------------------
extern "C" void kernel_launch(void* const* d_in, const int* in_sizes, int n_in,
                              void* d_out, int out_size)
{
    const float* data = (const float*)d_in[0];
    const float* Wg   = (const float*)d_in[1];
    const float* bg   = (const float*)d_in[2];
    const float* Wp   = (const float*)d_in[3];
    const float* bp   = (const float*)d_in[4];
    const float* qw   = (const float*)d_in[5];
    float* out = (float*)d_out;

    cudaFuncSetAttribute(sim_kernel,
                         cudaFuncAttributeMaxDynamicSharedMemorySize, 65536);

    dim3 gGrid(D_H / 128, BATCH / 128);
    gemm_relu_kernel<<<gGrid, 256>>>(data, Wg, bg);

    sim_kernel<<<BATCH / 2, 128, 65536>>>(Wp, bp, qw, out);
}

// round 5
// speedup vs baseline: 1.4078x; 1.1111x over previous
#include <cuda_runtime.h>
#include <cstdint>

// ---------------------------------------------------------------------------
#define BATCH   16384
#define D_IN    256
#define D_H     512
#define NQ      12
#define NLAYERS 4
#define FULLM   0xffffffffu

typedef unsigned long long ull;

// Scratch for h = relu(data @ W_graph + b_graph): 16384 x 512 fp32 = 32 MB
__device__ float g_h[(size_t)BATCH * D_H];

__host__ __device__ constexpr int cpop(int v) {
    int c = 0;
    for (int i = 0; i < 12; i++) c += (v >> i) & 1;
    return c;
}
__host__ __device__ constexpr int e5(int r) {            // 5-bit prefix-xor
    return (r ^ (r >> 1) ^ (r >> 2) ^ (r >> 3) ^ (r >> 4)) & 31;
}
__host__ __device__ constexpr int gray5(int r) { return (r ^ (r >> 1)) & 31; }

// ---- packed f32x2 helpers (sm_100a) ----
__device__ __forceinline__ ull pk2(float x, float y) {
    ull r; asm("mov.b64 %0, {%1,%2};" : "=l"(r) : "f"(x), "f"(y)); return r;
}
__device__ __forceinline__ ull pkb(float x) { return pk2(x, x); }
__device__ __forceinline__ void upk(ull v, float& x, float& y) {
    asm("mov.b64 {%0,%1}, %2;" : "=f"(x), "=f"(y) : "l"(v));
}
__device__ __forceinline__ ull fma2(ull a, ull b, ull c) {
    ull d; asm("fma.rn.f32x2 %0, %1, %2, %3;" : "=l"(d) : "l"(a), "l"(b), "l"(c)); return d;
}
__device__ __forceinline__ ull mul2(ull a, ull b) {
    ull d; asm("mul.rn.f32x2 %0, %1, %2;" : "=l"(d) : "l"(a), "l"(b)); return d;
}
__device__ __forceinline__ ull add2(ull a, ull b) {
    ull d; asm("add.rn.f32x2 %0, %1, %2;" : "=l"(d) : "l"(a), "l"(b)); return d;
}

// ---------------------------------------------------------------------------
// Kernel 1: h = relu(data @ W_graph + b_graph)  (unchanged)
// ---------------------------------------------------------------------------
__global__ void __launch_bounds__(256)
gemm_relu_kernel(const float* __restrict__ A,
                 const float* __restrict__ B,
                 const float* __restrict__ bias)
{
    __shared__ float As[8][128];
    __shared__ float Bs[8][128];

    const int tid = threadIdx.x;
    const int colBase = blockIdx.x * 128;
    const int rowBase = blockIdx.y * 128;

    const int innerRowA = tid >> 1;
    const int innerColA = (tid & 1) * 4;
    const int innerRowB = tid >> 5;
    const int innerColB = (tid & 31) * 4;

    const int tr = (tid >> 4) * 8;
    const int tc = (tid & 15) * 8;

    float acc[8][8];
#pragma unroll
    for (int i = 0; i < 8; i++)
#pragma unroll
        for (int j = 0; j < 8; j++) acc[i][j] = 0.f;

    const float* Aptr = A + (size_t)(rowBase + innerRowA) * D_IN + innerColA;
    const float* Bptr = B + (size_t)innerRowB * D_H + colBase + innerColB;

    for (int k0 = 0; k0 < D_IN; k0 += 8) {
        float4 av = *reinterpret_cast<const float4*>(Aptr + k0);
        float4 bv = *reinterpret_cast<const float4*>(Bptr + (size_t)k0 * D_H);

        As[innerColA + 0][innerRowA] = av.x;
        As[innerColA + 1][innerRowA] = av.y;
        As[innerColA + 2][innerRowA] = av.z;
        As[innerColA + 3][innerRowA] = av.w;
        *reinterpret_cast<float4*>(&Bs[innerRowB][innerColB]) = bv;
        __syncthreads();

#pragma unroll
        for (int kk = 0; kk < 8; kk++) {
            float ra[8], rb[8];
            float4 a0 = *reinterpret_cast<const float4*>(&As[kk][tr]);
            float4 a1 = *reinterpret_cast<const float4*>(&As[kk][tr + 4]);
            float4 b0 = *reinterpret_cast<const float4*>(&Bs[kk][tc]);
            float4 b1 = *reinterpret_cast<const float4*>(&Bs[kk][tc + 4]);
            ra[0] = a0.x; ra[1] = a0.y; ra[2] = a0.z; ra[3] = a0.w;
            ra[4] = a1.x; ra[5] = a1.y; ra[6] = a1.z; ra[7] = a1.w;
            rb[0] = b0.x; rb[1] = b0.y; rb[2] = b0.z; rb[3] = b0.w;
            rb[4] = b1.x; rb[5] = b1.y; rb[6] = b1.z; rb[7] = b1.w;
#pragma unroll
            for (int i = 0; i < 8; i++)
#pragma unroll
                for (int j = 0; j < 8; j++)
                    acc[i][j] = fmaf(ra[i], rb[j], acc[i][j]);
        }
        __syncthreads();
    }

#pragma unroll
    for (int i = 0; i < 8; i++) {
        const int row = rowBase + tr + i;
#pragma unroll
        for (int j = 0; j < 8; j += 4) {
            const int col = colBase + tc + j;
            float4 v;
            v.x = fmaxf(acc[i][j + 0] + bias[col + 0], 0.f);
            v.y = fmaxf(acc[i][j + 1] + bias[col + 1], 0.f);
            v.z = fmaxf(acc[i][j + 2] + bias[col + 2], 0.f);
            v.w = fmaxf(acc[i][j + 3] + bias[col + 3], 0.f);
            *reinterpret_cast<float4*>(&g_h[(size_t)row * D_H + col]) = v;
        }
    }
}

// ---------------------------------------------------------------------------
// Kernel 2: fused GEMM2 -> sim -> expectation. 2 samples per block (f32x2).
// Same algebra as R4; now single 32 KB trip buffer + launch_bounds(128,4)
// to raise occupancy from 3 to 4 blocks/SM.
// ---------------------------------------------------------------------------
__global__ void __launch_bounds__(128, 4)
sim_kernel(const float* __restrict__ Wp,   // [D_H, NQ]
           const float* __restrict__ bp,   // [NQ]
           const float* __restrict__ qw,   // [NLAYERS*NQ]
           float* __restrict__ out)        // [BATCH]
{
    extern __shared__ ull S0[];            // 4096 packed amplitudes (32 KB)
    __shared__ float qt[NLAYERS * NQ];
    __shared__ float cS[2][NQ], sS[2][NQ];
    __shared__ float xpart[2][2][NQ];
    __shared__ float2 redc[4];
    __shared__ float CfS;

    const int tid  = threadIdx.x;
    const int w    = tid >> 5;      // 0..3
    const int lane = tid & 31;
    const int s0   = blockIdx.x * 2;

    if (tid < NLAYERS * NQ) {
        float a = qw[tid] * 0.5f;
        float sv, cv;
        sincosf(a, &sv, &cv);
        qt[tid] = sv / cv;
    }
    if (tid == 0) {
        float C = 1.f;
        for (int i = NQ; i < NLAYERS * NQ; i++) C *= cosf(qw[i] * 0.5f);
        CfS = C;
    }

    // ---- GEMM2: warps {0,1} -> sample 0, {2,3} -> sample 1 (split K=512) ----
    {
        const float* hr = g_h + (size_t)(s0 + (w >> 1)) * D_H;
        float xa[NQ];
#pragma unroll
        for (int q = 0; q < NQ; q++) xa[q] = 0.f;
#pragma unroll
        for (int j = 0; j < 8; j++) {
            const int k = (w & 1) * 256 + j * 32 + lane;
            const float hv = hr[k];
            const float4* wr = reinterpret_cast<const float4*>(Wp + (size_t)k * NQ);
            float4 w0 = wr[0], w1 = wr[1], w2 = wr[2];
            xa[0]  = fmaf(hv, w0.x, xa[0]);
            xa[1]  = fmaf(hv, w0.y, xa[1]);
            xa[2]  = fmaf(hv, w0.z, xa[2]);
            xa[3]  = fmaf(hv, w0.w, xa[3]);
            xa[4]  = fmaf(hv, w1.x, xa[4]);
            xa[5]  = fmaf(hv, w1.y, xa[5]);
            xa[6]  = fmaf(hv, w1.z, xa[6]);
            xa[7]  = fmaf(hv, w1.w, xa[7]);
            xa[8]  = fmaf(hv, w2.x, xa[8]);
            xa[9]  = fmaf(hv, w2.y, xa[9]);
            xa[10] = fmaf(hv, w2.z, xa[10]);
            xa[11] = fmaf(hv, w2.w, xa[11]);
        }
#pragma unroll
        for (int q = 0; q < NQ; q++) {
            float v = xa[q];
#pragma unroll
            for (int o = 16; o; o >>= 1) v += __shfl_xor_sync(FULLM, v, o);
            if (lane == q) xpart[w >> 1][w & 1][q] = v;
        }
    }
    __syncthreads();
    if ((w & 1) == 0 && lane < NQ) {
        const int smp = w >> 1;
        float x = xpart[smp][0][lane] + xpart[smp][1][lane] + bp[lane];
        // merged: 0.5*(atan(x)+pi/2) + 0.5*qw[layer0, wire=lane]
        float half = fmaf(0.5f, atanf(x), 0.78539816339744831f)
                   + 0.5f * qw[lane];
        float sv, cv;
        sincosf(half, &sv, &cv);
        cS[smp][lane] = cv;
        sS[smp][lane] = sv;
    }
    __syncthreads();

    // ---- initial product state, layout A (includes merged layer-1 RYs) ----
    float bx = CfS, by = CfS;
#pragma unroll
    for (int b = 0; b < 5; b++) {
        const int wr = 11 - b;
        if ((lane >> b) & 1) { bx *= sS[0][wr]; by *= sS[1][wr]; }
        else                 { bx *= cS[0][wr]; by *= cS[1][wr]; }
    }
    if (w & 1)  { bx *= sS[0][6]; by *= sS[1][6]; }
    else        { bx *= cS[0][6]; by *= cS[1][6]; }
    if (w >> 1) { bx *= sS[0][5]; by *= sS[1][5]; }
    else        { bx *= cS[0][5]; by *= cS[1][5]; }

    ull st[32];
    st[0] = pk2(bx, by);
#pragma unroll
    for (int tb = 0; tb < 5; tb++) {
        const int wirew = 4 - tb;
        const ull cp = pk2(cS[0][wirew], cS[1][wirew]);
        const ull sp = pk2(sS[0][wirew], sS[1][wirew]);
#pragma unroll
        for (int r = 0; r < (1 << tb); r++) {
            st[r | (1 << tb)] = mul2(st[r], sp);
            st[r] = mul2(st[r], cp);
        }
    }

    // ---- precomputed smem address bases ----
    const int tA  = tid ^ ((tid >> 5) & 3);          // write/read layout-A base
    const int WB2 = (w << 10) | (lane << 5);         // write layout-B base
    int RB1;                                         // A->B-with-gray read base
    {
        const int n0 = WB2;
        const int g0 = n0 ^ (n0 >> 1);
        RB1 = g0 ^ ((g0 >> 5) & 31);
    }

    // ---- 3 remaining layers (single buffer, 4 barriers/layer) ----
#pragma unroll 1
    for (int ell = 0; ell < 3; ell++) {
        const int qb = NQ * (ell + 1);

        // trip: A -> B composed with gray perm
        __syncthreads();                 // WAR vs previous reads
#pragma unroll
        for (int r = 0; r < 32; r++)
            S0[(r << 7) + (tA ^ ((r & 7) << 2))] = st[r];
        __syncthreads();
#pragma unroll
        for (int r = 0; r < 32; r++)
            st[r] = S0[RB1 ^ gray5(r)];

        // wires 7..11 on layout-B reg bits (bt = 11-u)
#pragma unroll
        for (int u = 7; u < 12; u++) {
            const float t = qt[qb + u];
            const ull tp = pkb(t), np = pkb(-t);
            const int bt = 11 - u;
#pragma unroll
            for (int r = 0; r < 32; r++) {
                if (((r >> bt) & 1) == 0) {
                    const int j = r | (1 << bt);
                    const ull A = st[r], B = st[j];
                    st[r] = fma2(np, B, A);
                    st[j] = fma2(tp, A, B);
                }
            }
        }

        // wire 6 (lane bit 0) and wire 5 (lane bit 1): 64-bit shfl_xor
        {
            const float t6 = qt[qb + 6];
            const ull sg6 = (lane & 1) ? pkb(t6) : pkb(-t6);
#pragma unroll
            for (int r = 0; r < 32; r++) {
                const ull p = __shfl_xor_sync(FULLM, st[r], 1);
                st[r] = fma2(sg6, p, st[r]);
            }
            const float t5 = qt[qb + 5];
            const ull sg5 = ((lane >> 1) & 1) ? pkb(t5) : pkb(-t5);
#pragma unroll
            for (int r = 0; r < 32; r++) {
                const ull p = __shfl_xor_sync(FULLM, st[r], 2);
                st[r] = fma2(sg5, p, st[r]);
            }
        }

        // trip: B -> A
        __syncthreads();                 // WAR vs previous reads
#pragma unroll
        for (int r = 0; r < 32; r++)
            S0[WB2 | (lane ^ r)] = st[r];
        __syncthreads();
#pragma unroll
        for (int r = 0; r < 32; r++)
            st[r] = S0[(r << 7) + (tA ^ ((r & 7) << 2))];

        // wires 0..4 on layout-A reg bits (bt = 4-u)
#pragma unroll
        for (int u = 0; u < 5; u++) {
            const float t = qt[qb + u];
            const ull tp = pkb(t), np = pkb(-t);
            const int bt = 4 - u;
#pragma unroll
            for (int r = 0; r < 32; r++) {
                if (((r >> bt) & 1) == 0) {
                    const int j = r | (1 << bt);
                    const ull A = st[r], B = st[j];
                    st[r] = fma2(np, B, A);
                    st[j] = fma2(tp, A, B);
                }
            }
        }
    }

    // ---- measurement with final gray perm folded into the weights ----
    // weight(q) = 12 - 2*popc(E12(q)), q = (r<<7)|tid
    //           = A_r + s_r * 2*Pt,  Pt = popc(E7(tid))
    int ex = tid;
    ex ^= ex >> 1; ex ^= ex >> 2; ex ^= ex >> 4;
    const int Pt = __popc(ex & 127);

    ull acc1 = 0ull, accP = 0ull, accM = 0ull;
#pragma unroll
    for (int r = 0; r < 32; r++) {
        const int a = cpop(e5(r));
        const int p = cpop(r) & 1;
        const float Ar = p ? (float)(-2 - 2 * a) : (float)(12 - 2 * a);
        const ull t = mul2(st[r], st[r]);
        acc1 = fma2(pkb(Ar), t, acc1);
        if (p) accP = add2(accP, t);
        else   accM = add2(accM, t);
    }
    const ull S = fma2(pkb(-1.f), accM, accP);     // sum s_r * t_r
    const ull res = fma2(pkb(2.f * (float)Pt), S, acc1);

    float rx, ry;
    upk(res, rx, ry);
#pragma unroll
    for (int o = 16; o; o >>= 1) {
        rx += __shfl_xor_sync(FULLM, rx, o);
        ry += __shfl_xor_sync(FULLM, ry, o);
    }
    if (lane == 0) redc[w] = make_float2(rx, ry);
    __syncthreads();
    if (tid == 0) {
        out[s0]     = redc[0].x + redc[1].x + redc[2].x + redc[3].x;
        out[s0 + 1] = redc[0].y + redc[1].y + redc[2].y + redc[3].y;
    }
}

// ---------------------------------------------------------------------------
extern "C" void kernel_launch(void* const* d_in, const int* in_sizes, int n_in,
                              void* d_out, int out_size)
{
    const float* data = (const float*)d_in[0];
    const float* Wg   = (const float*)d_in[1];
    const float* bg   = (const float*)d_in[2];
    const float* Wp   = (const float*)d_in[3];
    const float* bp   = (const float*)d_in[4];
    const float* qw   = (const float*)d_in[5];
    float* out = (float*)d_out;

    dim3 gGrid(D_H / 128, BATCH / 128);
    gemm_relu_kernel<<<gGrid, 256>>>(data, Wg, bg);

    sim_kernel<<<BATCH / 2, 128, 32768>>>(Wp, bp, qw, out);
}